// round 12
// baseline (speedup 1.0000x reference)
#include <cuda_runtime.h>
#include <cuda_fp16.h>
#include <math.h>
#include <stdint.h>

// Problem constants
#define F 18
#define PP 128
#define HH 256
#define NCLS 625
#define NTOK (F*PP)            // 2304
#define NELEM (F*PP*HH)        // 589824
#define TOTROWS 22016          // 17*256 + 15*512 + 13*768
#define ROFF0 0
#define ROFF1 4352
#define ROFF2 12032
#define TPAIRS 1152            // NTOK/2
#define KG 768                 // gproj K dimension (3 scales x 256)

// -------- device scratch (allocation-free) --------
__device__ __half d_Xh[NELEM];             // fp16 inputs (for QKV mma)
__device__ __half d_Qh[3*NELEM];
__device__ __half d_Kh[3*NELEM];
__device__ uint32_t d_Vt[3*8*32*TPAIRS];   // [si][h][dim][tokpair] packed half2
__device__ __half d_attnh[TOTROWS*HH];     // attention output (fp16)
__device__ __half d_G[NTOK*KG];            // pregathered attn [token][si*256+k] fp16
__device__ __half d_Wqkvh[9*HH*HH];        // QKV weights transposed [si*3+which][n][k] fp16
__device__ __half d_Wgt[HH*KG];            // gproj weights [n][si*256+k] fp16
__device__ float d_bsum[HH];               // 0.25*(bo0+bo1+bo2)
__device__ float d_context[NELEM];
__device__ float d_sig[NTOK];
__device__ float d_ptn[F];
__device__ float d_Rt[F];
__device__ float d_w[F];
__device__ float d_partial[F*HH];

__device__ __forceinline__ uint32_t packh2(float a, float b) {
    __half2 h = __floats2half2_rn(a, b);
    return *(uint32_t*)&h;
}

__device__ __forceinline__ uint32_t h2ex2(uint32_t x) {
    uint32_t y;
    asm("ex2.approx.f16x2 %0, %1;" : "=r"(y) : "r"(x));
    return y;
}

__device__ __forceinline__ void cp16(uint32_t saddr, const void* g) {
    asm volatile("cp.async.cg.shared.global [%0], [%1], 16;\n" :: "r"(saddr), "l"(g));
}
#define CP_COMMIT() asm volatile("cp.async.commit_group;\n" ::: "memory")
#define CP_WAIT1()  asm volatile("cp.async.wait_group 1;\n" ::: "memory")
#define CP_WAIT0()  asm volatile("cp.async.wait_group 0;\n" ::: "memory")

// mma.sync m16n8k16 fp16 -> fp32 accumulate in-place
__device__ __forceinline__ void mma_f16(float c[4], const uint32_t a[4],
                                        uint32_t b0, uint32_t b1)
{
    asm volatile(
        "mma.sync.aligned.m16n8k16.row.col.f32.f16.f16.f32 "
        "{%0,%1,%2,%3}, {%4,%5,%6,%7}, {%8,%9}, {%0,%1,%2,%3};\n"
        : "+f"(c[0]), "+f"(c[1]), "+f"(c[2]), "+f"(c[3])
        : "r"(a[0]), "r"(a[1]), "r"(a[2]), "r"(a[3]), "r"(b0), "r"(b1));
}

// =================== halting iter-0 (fp32 embed): two positions per warp ===================
__global__ void __launch_bounds__(256)
halt_sig_k(const float* __restrict__ x, const float* __restrict__ hW,
           const float* __restrict__ hb, float* __restrict__ sig)
{
    int warp = threadIdx.x >> 5;
    int lane = threadIdx.x & 31;
    int pos = blockIdx.x * 8 + warp;      // [0, 1152); second position = pos + 1152
    const float* xp0 = x + (size_t)pos * HH + lane * 8;
    const float* xp1 = x + (size_t)(pos + TPAIRS) * HH + lane * 8;
    const float* wp = hW + lane * 8;
    float4 a0 = *(const float4*)xp0;
    float4 a1 = *(const float4*)(xp0 + 4);
    float4 b0 = *(const float4*)xp1;
    float4 b1 = *(const float4*)(xp1 + 4);
    float4 w0 = *(const float4*)wp;
    float4 w1 = *(const float4*)(wp + 4);
    float acc0 = a0.x * w0.x + a0.y * w0.y + a0.z * w0.z + a0.w * w0.w
               + a1.x * w1.x + a1.y * w1.y + a1.z * w1.z + a1.w * w1.w;
    float acc1 = b0.x * w0.x + b0.y * w0.y + b0.z * w0.z + b0.w * w0.w
               + b1.x * w1.x + b1.y * w1.y + b1.z * w1.z + b1.w * w1.w;
    #pragma unroll
    for (int off = 16; off > 0; off >>= 1) {
        acc0 += __shfl_xor_sync(0xffffffffu, acc0, off);
        acc1 += __shfl_xor_sync(0xffffffffu, acc1, off);
    }
    if (lane == 0) {
        sig[pos] = 1.f / (1.f + __expf(-(acc0 + hb[0])));
        sig[pos + TPAIRS] = 1.f / (1.f + __expf(-(acc1 + hb[0])));
    }
}

// =================== halting iter-1 (fp16 Xh): two positions per warp ===================
__global__ void __launch_bounds__(256)
halt_sig_h_k(const __half* __restrict__ Xh, const float* __restrict__ hW,
             const float* __restrict__ hb, float* __restrict__ sig)
{
    int warp = threadIdx.x >> 5;
    int lane = threadIdx.x & 31;
    int pos = blockIdx.x * 8 + warp;
    const uint32_t* x0 = (const uint32_t*)(Xh + (size_t)pos * HH) + lane * 4;
    const uint32_t* x1 = (const uint32_t*)(Xh + (size_t)(pos + TPAIRS) * HH) + lane * 4;
    const float* wp = hW + lane * 8;
    float acc0 = 0.f, acc1 = 0.f;
    #pragma unroll
    for (int j = 0; j < 4; j++) {
        uint32_t u0 = x0[j], u1 = x1[j];
        float2 a = __half22float2(*(__half2*)&u0);
        float2 b = __half22float2(*(__half2*)&u1);
        acc0 += a.x * wp[2*j] + a.y * wp[2*j+1];
        acc1 += b.x * wp[2*j] + b.y * wp[2*j+1];
    }
    #pragma unroll
    for (int off = 16; off > 0; off >>= 1) {
        acc0 += __shfl_xor_sync(0xffffffffu, acc0, off);
        acc1 += __shfl_xor_sync(0xffffffffu, acc1, off);
    }
    if (lane == 0) {
        sig[pos] = 1.f / (1.f + __expf(-(acc0 + hb[0])));
        sig[pos + TPAIRS] = 1.f / (1.f + __expf(-(acc1 + hb[0])));
    }
}

// =================== halting phase 2 (mean) + ACT, one block ===================
__global__ void __launch_bounds__(576)
act2_k(const float* __restrict__ sig, float* __restrict__ ptn,
       float* __restrict__ Rt, float* __restrict__ w, int first)
{
    int f = threadIdx.x >> 5;      // 0..17
    int lane = threadIdx.x & 31;
    const float4 v = *(const float4*)&sig[f * PP + lane * 4];
    float acc = v.x + v.y + v.z + v.w;
    #pragma unroll
    for (int off = 16; off > 0; off >>= 1)
        acc += __shfl_xor_sync(0xffffffffu, acc, off);
    if (lane == 0) {
        float pf = acc * (1.f / 128.f);
        float pt = first ? 0.f : ptn[f];
        float rt = first ? 0.f : Rt[f];
        float run = (pt < 1.0f) ? 1.f : 0.f;
        float t = pt + pf * run;
        float nh   = (t > 0.99f)  ? run : 0.f;
        float run2 = (t <= 0.99f) ? run : 0.f;
        pt = pt + pf * run2;
        rt = rt + nh * (1.f - pt);
        pt = pt + nh * rt;
        ptn[f] = pt; Rt[f] = rt;
        w[f] = pf * run2 + nh * rt;
    }
}

// =================== weight conversions ===================
__global__ void __launch_bounds__(256)
convwt_qkv_k(const float* __restrict__ Wq, const float* __restrict__ Wk,
             const float* __restrict__ Wv, __half* __restrict__ Wt)
{
    __shared__ float t[32][33];
    int z = blockIdx.z;              // 0..8
    int si = z / 3, which = z - si * 3;
    const float* W = (which == 0) ? Wq : ((which == 1) ? Wk : Wv);
    const float* src = W + (size_t)si * HH * HH;
    __half* dst = Wt + (size_t)z * HH * HH;
    int k0 = blockIdx.x * 32, n0 = blockIdx.y * 32;
    int tx = threadIdx.x, ty = threadIdx.y;
    #pragma unroll
    for (int r = ty; r < 32; r += 8)
        t[r][tx] = src[(size_t)(k0 + r) * HH + n0 + tx];
    __syncthreads();
    #pragma unroll
    for (int r = ty; r < 32; r += 8)
        dst[(size_t)(n0 + r) * HH + k0 + tx] = __float2half(t[tx][r]);
}

// gproj weights: Wo[si][k][n] -> Wgt[n][si*256+k]
__global__ void __launch_bounds__(256)
convwt_gproj_k(const float* __restrict__ Wo, __half* __restrict__ Wgt)
{
    __shared__ float t[32][33];
    int si = blockIdx.z;
    const float* src = Wo + (size_t)si * HH * HH;
    int k0 = blockIdx.x * 32, n0 = blockIdx.y * 32;
    int tx = threadIdx.x, ty = threadIdx.y;
    #pragma unroll
    for (int r = ty; r < 32; r += 8)
        t[r][tx] = src[(size_t)(k0 + r) * HH + n0 + tx];
    __syncthreads();
    #pragma unroll
    for (int r = ty; r < 32; r += 8)
        Wgt[(size_t)(n0 + r) * KG + si * HH + k0 + tx] = __float2half(t[tx][r]);
}

__global__ void bsum_k(const float* __restrict__ bo, float* __restrict__ bsum)
{
    int n = threadIdx.x;
    bsum[n] = 0.25f * (bo[n] + bo[HH + n] + bo[2 * HH + n]);
}

// =================== X -> fp16 ===================
__global__ void xconv_k(const float* __restrict__ X, __half* __restrict__ Xh)
{
    int i = blockIdx.x * 256 + threadIdx.x;
    float2 v = *(const float2*)&X[2 * i];
    *(uint32_t*)&Xh[2 * i] = packh2(v.x, v.y);
}

// =================== fp16 mma GEMM mainloop, tile 128x128, generic K ===================
// cp.async 2-stage pipeline. sbuf: 4 buffers of 128*OSTRIDE uint32: [As0][Bs0][As1][Bs1].
#define OSTRIDE 36
#define GBUF (128 * OSTRIDE)
__device__ __forceinline__ void mma_mainloop(const __half* __restrict__ A, int bm, int lda,
                                             const __half* __restrict__ Bw, int bn, int ldb,
                                             int kdim, uint32_t* sbuf, float acc[2][8][4])
{
    const int tid  = threadIdx.x;
    const int warp = tid >> 5;
    const int lane = tid & 31;
    const int gid  = lane >> 2;
    const int tig  = lane & 3;
    const int wm = (warp & 3) * 32;
    const int wn = (warp >> 2) * 64;
    const uint32_t sb = (uint32_t)__cvta_generic_to_shared(sbuf);

    #pragma unroll
    for (int mt = 0; mt < 2; mt++)
        #pragma unroll
        for (int nt = 0; nt < 8; nt++)
            #pragma unroll
            for (int i = 0; i < 4; i++) acc[mt][nt][i] = 0.f;

    auto issue = [&](int kc, int st) {
        uint32_t aoff = sb + (uint32_t)(2 * st) * (GBUF * 4);
        uint32_t boff = aoff + GBUF * 4;
        for (int i = tid; i < 1024; i += 256) {
            int m = i >> 3, q = i & 7;
            uint32_t so = (uint32_t)(m * OSTRIDE + q * 4) * 4;
            cp16(aoff + so, &A[(size_t)(bm + m) * lda + kc + q * 8]);
            cp16(boff + so, &Bw[(size_t)(bn + m) * ldb + kc + q * 8]);
        }
        CP_COMMIT();
    };

    const int nchunks = kdim >> 6;
    issue(0, 0);
    for (int kci = 0; kci < nchunks; kci++) {
        const bool more = (kci + 1) < nchunks;
        if (more) issue((kci + 1) * 64, (kci + 1) & 1);
        if (more) CP_WAIT1(); else CP_WAIT0();
        __syncthreads();
        uint32_t* As = sbuf + 2 * (kci & 1) * GBUF;
        uint32_t* Bs = As + GBUF;
        #pragma unroll
        for (int ks = 0; ks < 4; ks++) {
            uint32_t a[2][4];
            #pragma unroll
            for (int mt = 0; mt < 2; mt++) {
                int r0 = (wm + mt * 16 + gid) * OSTRIDE + ks * 8;
                int r1 = (wm + mt * 16 + gid + 8) * OSTRIDE + ks * 8;
                a[mt][0] = As[r0 + tig];
                a[mt][1] = As[r1 + tig];
                a[mt][2] = As[r0 + tig + 4];
                a[mt][3] = As[r1 + tig + 4];
            }
            #pragma unroll
            for (int nt = 0; nt < 8; nt++) {
                int nr = (wn + nt * 8 + gid) * OSTRIDE + ks * 8;
                uint32_t b0 = Bs[nr + tig];
                uint32_t b1 = Bs[nr + tig + 4];
                #pragma unroll
                for (int mt = 0; mt < 2; mt++)
                    mma_f16(acc[mt][nt], a[mt], b0, b1);
            }
        }
        __syncthreads();
    }
}

// QKV mma GEMM: grid (18, 2, 9); z: si=z/3, which=z%3.
__global__ void __launch_bounds__(256)
gemm_qkv_mma_k(const __half* __restrict__ Xh, const __half* __restrict__ Wt,
               const float* __restrict__ bq, const float* __restrict__ bk,
               const float* __restrict__ bv,
               __half* __restrict__ Q, __half* __restrict__ K,
               uint32_t* __restrict__ Vt)
{
    __shared__ uint32_t sbuf[4 * GBUF];
    int z = blockIdx.z;
    int si = z / 3, which = z - si * 3;
    int bm = blockIdx.x * 128, bn = blockIdx.y * 128;

    float acc[2][8][4];
    mma_mainloop(Xh, bm, HH, Wt + (size_t)z * HH * HH, bn, HH, HH, sbuf, acc);

    const int tid  = threadIdx.x;
    const int warp = tid >> 5;
    const int lane = tid & 31;
    const int gid  = lane >> 2;
    const int tig  = lane & 3;
    const int wm = (warp & 3) * 32;
    const int wn = (warp >> 2) * 64;

    if (which < 2) {
        const float* bias = ((which == 0) ? bq : bk) + si * HH;
        __half* C = ((which == 0) ? Q : K) + (size_t)si * NELEM;
        float oscale = (which == 0) ? (0.17677669529663687f * 1.4426950408889634f) : 1.0f;
        #pragma unroll
        for (int nt = 0; nt < 8; nt++) {
            int n = bn + wn + nt * 8 + 2 * tig;
            float b0 = bias[n], b1 = bias[n + 1];
            #pragma unroll
            for (int mt = 0; mt < 2; mt++) {
                int m = bm + wm + mt * 16 + gid;
                *(uint32_t*)&C[(size_t)m * 256 + n] =
                    packh2((acc[mt][nt][0] + b0) * oscale, (acc[mt][nt][1] + b1) * oscale);
                *(uint32_t*)&C[(size_t)(m + 8) * 256 + n] =
                    packh2((acc[mt][nt][2] + b0) * oscale, (acc[mt][nt][3] + b1) * oscale);
            }
        }
    } else {
        // stage fp16 tile [tok][dim] in smem, then write transposed packed Vt
        const float* bias = bv + si * HH;
        __half* stag = (__half*)sbuf;            // [128 tok][stride 130]
        __syncthreads();
        #pragma unroll
        for (int nt = 0; nt < 8; nt++) {
            int nl = wn + nt * 8 + 2 * tig;
            float b0 = bias[bn + nl], b1 = bias[bn + nl + 1];
            #pragma unroll
            for (int mt = 0; mt < 2; mt++) {
                int ml = wm + mt * 16 + gid;
                *(uint32_t*)&stag[ml * 130 + nl] =
                    packh2(acc[mt][nt][0] + b0, acc[mt][nt][1] + b1);
                *(uint32_t*)&stag[(ml + 8) * 130 + nl] =
                    packh2(acc[mt][nt][2] + b0, acc[mt][nt][3] + b1);
            }
        }
        __syncthreads();
        const int tpg0 = bm >> 1;
        uint32_t* vtb = Vt + (size_t)si * 8 * 32 * TPAIRS;
        #pragma unroll
        for (int j = tid; j < 8192; j += 256) {
            int tp = j & 63;
            int nl = j >> 6;
            int ncol = bn + nl;
            int h = ncol >> 5, d = ncol & 31;
            __half lo = stag[(2 * tp) * 130 + nl];
            __half hi = stag[(2 * tp + 1) * 130 + nl];
            __half2 pr = __halves2half2(lo, hi);
            vtb[((size_t)(h * 32 + d)) * TPAIRS + tpg0 + tp] = *(uint32_t*)&pr;
        }
    }
}

// =================== pregather: overlap-add average of attnh rows (fp16) ===================
// G[token][si*256+k] = (0.25/count) * sum_w attnh[row(w)][k]
__global__ void __launch_bounds__(256)
pregather_k(const __half* __restrict__ attnh, __half* __restrict__ G)
{
    int idx = blockIdx.x * 256 + threadIdx.x;   // [0, 2304*384)
    int t = idx / 384;
    int c2 = idx - t * 384;
    int si = c2 >> 7;
    int kp = c2 & 127;
    int f = t >> 7, pos = t & 127;

    const int sc[3] = {2, 4, 6};
    const int Ss[3] = {256, 512, 768};
    const int ro[3] = {ROFF0, ROFF1, ROFF2};
    int s = sc[si], S = Ss[si];
    int nw = F - s + 1;
    int wlo = max(0, f - s + 1);
    int whi = min(f, nw - 1);
    float s0 = 0.f, s1 = 0.f;
    for (int ww = wlo; ww <= whi; ww++) {
        int r = ro[si] + ww * S + (f - ww) * PP + pos;
        uint32_t v = *(const uint32_t*)&attnh[(size_t)r * HH + kp * 2];
        float2 fv = __half22float2(*(__half2*)&v);
        s0 += fv.x; s1 += fv.y;
    }
    float wt = 0.25f / (float)(whi - wlo + 1);
    *(uint32_t*)&G[(size_t)t * KG + si * HH + kp * 2] = packh2(s0 * wt, s1 * wt);
}

// =================== gproj GEMM [2304x768]@[768x256] + fused finalize ===================
// grid (18, 2). Epilogue: v = acc + bsum[n]; context update (w[f] tile-uniform);
// fp16 Xh write (input for next iteration's QKV).
__global__ void __launch_bounds__(256)
gemm_gproj_mma_k(const __half* __restrict__ G, const __half* __restrict__ Wgt,
                 const float* __restrict__ bsum, const float* __restrict__ w,
                 float* __restrict__ context, __half* __restrict__ Xh, int first)
{
    __shared__ uint32_t sbuf[4 * GBUF];
    int bm = blockIdx.x * 128, bn = blockIdx.y * 128;

    float acc[2][8][4];
    mma_mainloop(G, bm, KG, Wgt, bn, KG, KG, sbuf, acc);

    const int tid  = threadIdx.x;
    const int warp = tid >> 5;
    const int lane = tid & 31;
    const int gid  = lane >> 2;
    const int tig  = lane & 3;
    const int wm = (warp & 3) * 32;
    const int wn = (warp >> 2) * 64;

    const int f = bm >> 7;             // one frame per 128-row tile
    const float wwf = w[f];
    const float cwf = 1.f - wwf;

    #pragma unroll
    for (int nt = 0; nt < 8; nt++) {
        int n = bn + wn + nt * 8 + 2 * tig;
        float b0 = bsum[n], b1 = bsum[n + 1];
        #pragma unroll
        for (int mt = 0; mt < 2; mt++) {
            int m = bm + wm + mt * 16 + gid;
            {
                float v0 = acc[mt][nt][0] + b0, v1 = acc[mt][nt][1] + b1;
                size_t idx = (size_t)m * 256 + n;
                float2 c = first ? make_float2(0.f, 0.f) : *(float2*)&context[idx];
                *(float2*)&context[idx] = make_float2(v0 * wwf + c.x * cwf,
                                                      v1 * wwf + c.y * cwf);
                *(uint32_t*)&Xh[idx] = packh2(v0, v1);
            }
            {
                float v0 = acc[mt][nt][2] + b0, v1 = acc[mt][nt][3] + b1;
                size_t idx = (size_t)(m + 8) * 256 + n;
                float2 c = first ? make_float2(0.f, 0.f) : *(float2*)&context[idx];
                *(float2*)&context[idx] = make_float2(v0 * wwf + c.x * cwf,
                                                      v1 * wwf + c.y * cwf);
                *(uint32_t*)&Xh[idx] = packh2(v0, v1);
            }
        }
    }
}

// =================== tensor-core flash attention, hd=32, all fp16 mma ===================
#define KPSTRIDE 36
#define VTSTRIDE 36
__global__ void __launch_bounds__(256, 3)
attn_mma_k(const __half* __restrict__ Qg, const __half* __restrict__ Kg,
           const uint32_t* __restrict__ Vt, __half* __restrict__ O)
{
    __shared__ uint32_t Kp[2][64 * KPSTRIDE];   // [stage][key][kpair]
    __shared__ uint32_t Vs[2][32 * VTSTRIDE];   // [stage][dim][keypair]

    const int tid  = threadIdx.x;
    const int warp = tid >> 5;
    const int lane = tid & 31;
    const int gid  = lane >> 2;
    const int tig  = lane & 3;
    const int h    = blockIdx.y;

    int pid = blockIdx.x;
    int si, S, w, j0, rowoff;
    if (pid < 78)       { si = 2; S = 768; w = pid / 6;  j0 = (pid - w * 6) << 7; rowoff = ROFF2; }
    else if (pid < 138) { pid -= 78;  si = 1; S = 512; w = pid >> 2; j0 = (pid & 3) << 7; rowoff = ROFF1; }
    else                { pid -= 138; si = 0; S = 256; w = pid >> 1; j0 = (pid & 1) << 7; rowoff = ROFF0; }

    const __half* Q = Qg + (size_t)si * NELEM;
    const __half* K = Kg + (size_t)si * NELEM;
    const uint32_t* Vtb = Vt + ((size_t)si * 8 + h) * 32 * TPAIRS;

    const uint32_t kpb = (uint32_t)__cvta_generic_to_shared(&Kp[0][0]);
    const uint32_t vsb = (uint32_t)__cvta_generic_to_shared(&Vs[0][0]);

    auto issueKV = [&](int kb, int st) {
        {
            const __half* kg = K + ((size_t)(w * PP + kb)) * HH + h * 32;
            int key = tid >> 2, q = tid & 3;
            cp16(kpb + (uint32_t)(st * 64 * KPSTRIDE + key * KPSTRIDE + q * 4) * 4,
                 kg + (size_t)key * HH + q * 8);
        }
        {
            const uint32_t* vg = Vtb + ((w * PP + kb) >> 1);
            int d = tid >> 3, q = tid & 7;
            cp16(vsb + (uint32_t)(st * 32 * VTSTRIDE + d * VTSTRIDE + q * 4) * 4,
                 vg + (size_t)d * TPAIRS + q * 4);
        }
        CP_COMMIT();
    };

    const int qrow = w * PP + j0 + warp * 16 + gid;
    uint32_t qa[2][4];
    #pragma unroll
    for (int ks = 0; ks < 2; ks++) {
        const uint32_t* q0 = (const uint32_t*)(Q + (size_t)qrow * HH + h * 32 + ks * 16);
        const uint32_t* q1 = (const uint32_t*)(Q + (size_t)(qrow + 8) * HH + h * 32 + ks * 16);
        qa[ks][0] = q0[tig];
        qa[ks][1] = q1[tig];
        qa[ks][2] = q0[tig + 4];
        qa[ks][3] = q1[tig + 4];
    }

    float o[4][4];
    #pragma unroll
    for (int v = 0; v < 4; v++)
        #pragma unroll
        for (int i = 0; i < 4; i++) o[v][i] = 0.f;
    float l0 = 0.f, l1 = 0.f;

    issueKV(0, 0);
    for (int kb = 0; kb < S; kb += 64) {
        const int st = (kb >> 6) & 1;
        const bool more = (kb + 64) < S;
        if (more) issueKV(kb + 64, st ^ 1);
        if (more) CP_WAIT1(); else CP_WAIT0();
        __syncthreads();

        float s[8][4];
        #pragma unroll
        for (int t = 0; t < 8; t++) {
            s[t][0] = s[t][1] = s[t][2] = s[t][3] = 0.f;
            const int krow = (8 * t + gid) * KPSTRIDE;
            #pragma unroll
            for (int ks = 0; ks < 2; ks++) {
                uint32_t b0 = Kp[st][krow + ks * 8 + tig];
                uint32_t b1 = Kp[st][krow + ks * 8 + tig + 4];
                mma_f16(s[t], qa[ks], b0, b1);
            }
        }

        uint32_t e0[8], e1[8];
        #pragma unroll
        for (int t = 0; t < 8; t++) {
            e0[t] = h2ex2(packh2(s[t][0], s[t][1]));
            e1[t] = h2ex2(packh2(s[t][2], s[t][3]));
            float2 f0 = __half22float2(*(__half2*)&e0[t]);
            float2 f1 = __half22float2(*(__half2*)&e1[t]);
            l0 += f0.x + f0.y;
            l1 += f1.x + f1.y;
        }

        #pragma unroll
        for (int u = 0; u < 4; u++) {
            uint32_t pa[4];
            pa[0] = e0[2*u];
            pa[1] = e1[2*u];
            pa[2] = e0[2*u+1];
            pa[3] = e1[2*u+1];
            #pragma unroll
            for (int v = 0; v < 4; v++) {
                uint32_t b0 = Vs[st][(gid + 8 * v) * VTSTRIDE + 8 * u + tig];
                uint32_t b1 = Vs[st][(gid + 8 * v) * VTSTRIDE + 8 * u + tig + 4];
                mma_f16(o[v], pa, b0, b1);
            }
        }
        __syncthreads();
    }

    l0 += __shfl_xor_sync(0xffffffffu, l0, 1);
    l0 += __shfl_xor_sync(0xffffffffu, l0, 2);
    l1 += __shfl_xor_sync(0xffffffffu, l1, 1);
    l1 += __shfl_xor_sync(0xffffffffu, l1, 2);
    float il0 = 1.f / l0, il1 = 1.f / l1;

    const int orow = rowoff + w * S + j0 + warp * 16 + gid;
    #pragma unroll
    for (int v = 0; v < 4; v++) {
        *(uint32_t*)&O[(size_t)orow * HH + h * 32 + v * 8 + 2 * tig] =
            packh2(o[v][0] * il0, o[v][1] * il0);
        *(uint32_t*)&O[(size_t)(orow + 8) * HH + h * 32 + v * 8 + 2 * tig] =
            packh2(o[v][2] * il1, o[v][3] * il1);
    }
}

// =================== context reduction + classifier ===================
__global__ void ctxpart_k(const float* __restrict__ context, float* __restrict__ partial)
{
    int f = blockIdx.x;
    int h = threadIdx.x;          // 256
    float s = 0.f;
    const float* cp = context + (size_t)f * PP * HH + h;
    #pragma unroll 4
    for (int pos = 0; pos < PP; pos++) s += cp[(size_t)pos * HH];
    partial[f * HH + h] = s;
}

__global__ void classify_k(const float* __restrict__ partial, const float* __restrict__ clsW,
                           const float* __restrict__ clsb, float* __restrict__ out)
{
    __shared__ float cs[HH];
    int tid = threadIdx.x;        // 128
    for (int h = tid; h < HH; h += 128) {
        float s = 0.f;
        #pragma unroll
        for (int f = 0; f < F; f++) s += partial[f * HH + h];
        cs[h] = s;
    }
    __syncthreads();
    int j = blockIdx.x * 128 + tid;
    if (j < NCLS) {
        float acc = clsb[j];
        for (int h = 0; h < HH; h++) acc = fmaf(cs[h], clsW[h * NCLS + j], acc);
        out[j] = acc;
    }
}

// =================== host launch ===================
extern "C" void kernel_launch(void* const* d_in, const int* in_sizes, int n_in,
                              void* d_out, int out_size)
{
    (void)in_sizes; (void)n_in; (void)out_size;
    const float* embed  = (const float*)d_in[0];
    const float* halt_W = (const float*)d_in[3];
    const float* halt_b = (const float*)d_in[4];
    const float* cls_W  = (const float*)d_in[8];
    const float* cls_b  = (const float*)d_in[9];
    const float* Wq = (const float*)d_in[10];
    const float* bq = (const float*)d_in[11];
    const float* Wk = (const float*)d_in[12];
    const float* bk = (const float*)d_in[13];
    const float* Wv = (const float*)d_in[14];
    const float* bv = (const float*)d_in[15];
    const float* Wo = (const float*)d_in[16];
    const float* bo = (const float*)d_in[17];
    float* out = (float*)d_out;

    float *context, *sig, *ptn, *Rt, *w, *partial, *bsum;
    __half *Xh, *Qh, *Kh, *attnh, *G, *Wqkvh, *Wgt;
    uint32_t *Vt;
    cudaGetSymbolAddress((void**)&Xh,      d_Xh);
    cudaGetSymbolAddress((void**)&Qh,      d_Qh);
    cudaGetSymbolAddress((void**)&Kh,      d_Kh);
    cudaGetSymbolAddress((void**)&Vt,      d_Vt);
    cudaGetSymbolAddress((void**)&attnh,   d_attnh);
    cudaGetSymbolAddress((void**)&G,       d_G);
    cudaGetSymbolAddress((void**)&Wqkvh,   d_Wqkvh);
    cudaGetSymbolAddress((void**)&Wgt,     d_Wgt);
    cudaGetSymbolAddress((void**)&bsum,    d_bsum);
    cudaGetSymbolAddress((void**)&context, d_context);
    cudaGetSymbolAddress((void**)&sig,     d_sig);
    cudaGetSymbolAddress((void**)&ptn,     d_ptn);
    cudaGetSymbolAddress((void**)&Rt,      d_Rt);
    cudaGetSymbolAddress((void**)&w,       d_w);
    cudaGetSymbolAddress((void**)&partial, d_partial);

    // weight conversions (once per call)
    {
        dim3 b(32, 8);
        dim3 gq(8, 8, 9);
        convwt_qkv_k<<<gq, b>>>(Wq, Wk, Wv, Wqkvh);
        dim3 gg(8, 8, 3);
        convwt_gproj_k<<<gg, b>>>(Wo, Wgt);
        bsum_k<<<1, 256>>>(bo, bsum);
    }
    // X fp16 + halting sigmoid for iter 0
    xconv_k<<<NELEM / 512, 256>>>(embed, Xh);
    halt_sig_k<<<TPAIRS / 8, 256>>>(embed, halt_W, halt_b, sig);

    for (int iter = 0; iter < 2; iter++) {
        act2_k<<<1, 576>>>(sig, ptn, Rt, w, iter == 0 ? 1 : 0);

        // QKV (fp16 tensor GEMM) for all 3 scales; V written transposed (Vt)
        dim3 gq(NTOK / 128, 2, 9);
        gemm_qkv_mma_k<<<gq, 256>>>(Xh, Wqkvh, bq, bk, bv, Qh, Kh, Vt);

        // tensor-core attention, all scales: 172 pairs x 8 heads, 128 q/block
        dim3 ga(172, 8);
        attn_mma_k<<<ga, 256>>>(Qh, Kh, Vt, attnh);

        // overlap-add average of attn rows (before projection; linearity)
        pregather_k<<<(NTOK * 384) / 256, 256>>>(attnh, G);

        // single fused projection GEMM [2304x768]@[768x256] + finalize epilogue
        dim3 gg(NTOK / 128, 2);
        gemm_gproj_mma_k<<<gg, 256>>>(G, Wgt, bsum, w, context, Xh, iter == 0 ? 1 : 0);

        // halting sigmoid for next iteration (reads fp16 Xh)
        if (iter == 0)
            halt_sig_h_k<<<TPAIRS / 8, 256>>>(Xh, halt_W, halt_b, sig);
    }
    ctxpart_k<<<F, HH>>>(context, partial);
    classify_k<<<(NCLS + 127) / 128, 128>>>(partial, cls_W, cls_b, out);
}

// round 13
// speedup vs baseline: 1.0917x; 1.0917x over previous
#include <cuda_runtime.h>
#include <cuda_fp16.h>
#include <math.h>
#include <stdint.h>

// Problem constants
#define F 18
#define PP 128
#define HH 256
#define NCLS 625
#define NTOK (F*PP)            // 2304
#define NELEM (F*PP*HH)        // 589824
#define TOTROWS 22016          // 17*256 + 15*512 + 13*768
#define ROFF0 0
#define ROFF1 4352
#define ROFF2 12032
#define TPAIRS 1152            // NTOK/2
#define KG 768                 // gproj K dimension (3 scales x 256)

// -------- device scratch (allocation-free) --------
__device__ __half d_Xh[NELEM];             // fp16 inputs (for QKV mma)
__device__ __half d_Qh[3*NELEM];
__device__ __half d_Kh[3*NELEM];
__device__ uint32_t d_Vt[3*8*32*TPAIRS];   // [si][h][dim][tokpair] packed half2
__device__ __half d_attnh[TOTROWS*HH];     // attention output (fp16)
__device__ __half d_G[NTOK*KG];            // pregathered attn [token][si*256+k] fp16
__device__ __half d_Wqkvh[9*HH*HH];        // QKV weights transposed [si*3+which][n][k] fp16
__device__ __half d_Wgt[HH*KG];            // gproj weights [n][si*256+k] fp16
__device__ float d_bsum[HH];               // 0.25*(bo0+bo1+bo2)
__device__ float d_vsum[2*F*HH];           // per-iter per-frame column sums of gproj acc
__device__ float d_sig[NTOK];
__device__ float d_ptn[F];
__device__ float d_Rt[F];
__device__ float d_warr[2*F];

__device__ __forceinline__ uint32_t packh2(float a, float b) {
    __half2 h = __floats2half2_rn(a, b);
    return *(uint32_t*)&h;
}

__device__ __forceinline__ uint32_t h2ex2(uint32_t x) {
    uint32_t y;
    asm("ex2.approx.f16x2 %0, %1;" : "=r"(y) : "r"(x));
    return y;
}

__device__ __forceinline__ void cp16(uint32_t saddr, const void* g) {
    asm volatile("cp.async.cg.shared.global [%0], [%1], 16;\n" :: "r"(saddr), "l"(g));
}
#define CP_COMMIT() asm volatile("cp.async.commit_group;\n" ::: "memory")
#define CP_WAIT1()  asm volatile("cp.async.wait_group 1;\n" ::: "memory")
#define CP_WAIT0()  asm volatile("cp.async.wait_group 0;\n" ::: "memory")

// mma.sync m16n8k16 fp16 -> fp32 accumulate in-place
__device__ __forceinline__ void mma_f16(float c[4], const uint32_t a[4],
                                        uint32_t b0, uint32_t b1)
{
    asm volatile(
        "mma.sync.aligned.m16n8k16.row.col.f32.f16.f16.f32 "
        "{%0,%1,%2,%3}, {%4,%5,%6,%7}, {%8,%9}, {%0,%1,%2,%3};\n"
        : "+f"(c[0]), "+f"(c[1]), "+f"(c[2]), "+f"(c[3])
        : "r"(a[0]), "r"(a[1]), "r"(a[2]), "r"(a[3]), "r"(b0), "r"(b1));
}

// =================== iter-0 halting + X->fp16 (fused; both read embed) ===================
__global__ void __launch_bounds__(256)
halt_sig_k(const float* __restrict__ x, const float* __restrict__ hW,
           const float* __restrict__ hb, float* __restrict__ sig,
           __half* __restrict__ Xh)
{
    int warp = threadIdx.x >> 5;
    int lane = threadIdx.x & 31;
    int pos = blockIdx.x * 8 + warp;      // [0, 1152); second position = pos + 1152
    const float* xp0 = x + (size_t)pos * HH + lane * 8;
    const float* xp1 = x + (size_t)(pos + TPAIRS) * HH + lane * 8;
    const float* wp = hW + lane * 8;
    float4 a0 = *(const float4*)xp0;
    float4 a1 = *(const float4*)(xp0 + 4);
    float4 b0 = *(const float4*)xp1;
    float4 b1 = *(const float4*)(xp1 + 4);
    float4 w0 = *(const float4*)wp;
    float4 w1 = *(const float4*)(wp + 4);
    // fp16 X writes (16B per position per thread)
    uint4 ha, hb4;
    ha.x = packh2(a0.x, a0.y);  ha.y = packh2(a0.z, a0.w);
    ha.z = packh2(a1.x, a1.y);  ha.w = packh2(a1.z, a1.w);
    hb4.x = packh2(b0.x, b0.y); hb4.y = packh2(b0.z, b0.w);
    hb4.z = packh2(b1.x, b1.y); hb4.w = packh2(b1.z, b1.w);
    *(uint4*)&Xh[(size_t)pos * HH + lane * 8] = ha;
    *(uint4*)&Xh[(size_t)(pos + TPAIRS) * HH + lane * 8] = hb4;

    float acc0 = a0.x * w0.x + a0.y * w0.y + a0.z * w0.z + a0.w * w0.w
               + a1.x * w1.x + a1.y * w1.y + a1.z * w1.z + a1.w * w1.w;
    float acc1 = b0.x * w0.x + b0.y * w0.y + b0.z * w0.z + b0.w * w0.w
               + b1.x * w1.x + b1.y * w1.y + b1.z * w1.z + b1.w * w1.w;
    #pragma unroll
    for (int off = 16; off > 0; off >>= 1) {
        acc0 += __shfl_xor_sync(0xffffffffu, acc0, off);
        acc1 += __shfl_xor_sync(0xffffffffu, acc1, off);
    }
    if (lane == 0) {
        sig[pos] = 1.f / (1.f + __expf(-(acc0 + hb[0])));
        sig[pos + TPAIRS] = 1.f / (1.f + __expf(-(acc1 + hb[0])));
    }
}

// =================== iter-1 halting (fp16 Xh) ===================
__global__ void __launch_bounds__(256)
halt_sig_h_k(const __half* __restrict__ Xh, const float* __restrict__ hW,
             const float* __restrict__ hb, float* __restrict__ sig)
{
    int warp = threadIdx.x >> 5;
    int lane = threadIdx.x & 31;
    int pos = blockIdx.x * 8 + warp;
    const uint32_t* x0 = (const uint32_t*)(Xh + (size_t)pos * HH) + lane * 4;
    const uint32_t* x1 = (const uint32_t*)(Xh + (size_t)(pos + TPAIRS) * HH) + lane * 4;
    const float* wp = hW + lane * 8;
    float acc0 = 0.f, acc1 = 0.f;
    #pragma unroll
    for (int j = 0; j < 4; j++) {
        uint32_t u0 = x0[j], u1 = x1[j];
        float2 a = __half22float2(*(__half2*)&u0);
        float2 b = __half22float2(*(__half2*)&u1);
        acc0 += a.x * wp[2*j] + a.y * wp[2*j+1];
        acc1 += b.x * wp[2*j] + b.y * wp[2*j+1];
    }
    #pragma unroll
    for (int off = 16; off > 0; off >>= 1) {
        acc0 += __shfl_xor_sync(0xffffffffu, acc0, off);
        acc1 += __shfl_xor_sync(0xffffffffu, acc1, off);
    }
    if (lane == 0) {
        sig[pos] = 1.f / (1.f + __expf(-(acc0 + hb[0])));
        sig[pos + TPAIRS] = 1.f / (1.f + __expf(-(acc1 + hb[0])));
    }
}

// =================== halting phase 2 (mean) + ACT + vsum zero, one block ===================
__global__ void __launch_bounds__(576)
act2_k(const float* __restrict__ sig, float* __restrict__ ptn,
       float* __restrict__ Rt, float* __restrict__ warr,
       float* __restrict__ vsum, int iter)
{
    // zero this iteration's vsum slice
    for (int i = threadIdx.x; i < F * HH; i += 576)
        vsum[iter * F * HH + i] = 0.f;

    int f = threadIdx.x >> 5;      // 0..17
    int lane = threadIdx.x & 31;
    const float4 v = *(const float4*)&sig[f * PP + lane * 4];
    float acc = v.x + v.y + v.z + v.w;
    #pragma unroll
    for (int off = 16; off > 0; off >>= 1)
        acc += __shfl_xor_sync(0xffffffffu, acc, off);
    if (lane == 0 && f < F) {
        float pf = acc * (1.f / 128.f);
        float pt = iter == 0 ? 0.f : ptn[f];
        float rt = iter == 0 ? 0.f : Rt[f];
        float run = (pt < 1.0f) ? 1.f : 0.f;
        float t = pt + pf * run;
        float nh   = (t > 0.99f)  ? run : 0.f;
        float run2 = (t <= 0.99f) ? run : 0.f;
        pt = pt + pf * run2;
        rt = rt + nh * (1.f - pt);
        pt = pt + nh * rt;
        ptn[f] = pt; Rt[f] = rt;
        warr[iter * F + f] = pf * run2 + nh * rt;
    }
}

// =================== weight conversions ===================
__global__ void __launch_bounds__(256)
convwt_qkv_k(const float* __restrict__ Wq, const float* __restrict__ Wk,
             const float* __restrict__ Wv, __half* __restrict__ Wt)
{
    __shared__ float t[32][33];
    int z = blockIdx.z;              // 0..8
    int si = z / 3, which = z - si * 3;
    const float* W = (which == 0) ? Wq : ((which == 1) ? Wk : Wv);
    const float* src = W + (size_t)si * HH * HH;
    __half* dst = Wt + (size_t)z * HH * HH;
    int k0 = blockIdx.x * 32, n0 = blockIdx.y * 32;
    int tx = threadIdx.x, ty = threadIdx.y;
    #pragma unroll
    for (int r = ty; r < 32; r += 8)
        t[r][tx] = src[(size_t)(k0 + r) * HH + n0 + tx];
    __syncthreads();
    #pragma unroll
    for (int r = ty; r < 32; r += 8)
        dst[(size_t)(n0 + r) * HH + k0 + tx] = __float2half(t[tx][r]);
}

// gproj weights: Wo[si][k][n] -> Wgt[n][si*256+k]
__global__ void __launch_bounds__(256)
convwt_gproj_k(const float* __restrict__ Wo, __half* __restrict__ Wgt)
{
    __shared__ float t[32][33];
    int si = blockIdx.z;
    const float* src = Wo + (size_t)si * HH * HH;
    int k0 = blockIdx.x * 32, n0 = blockIdx.y * 32;
    int tx = threadIdx.x, ty = threadIdx.y;
    #pragma unroll
    for (int r = ty; r < 32; r += 8)
        t[r][tx] = src[(size_t)(k0 + r) * HH + n0 + tx];
    __syncthreads();
    #pragma unroll
    for (int r = ty; r < 32; r += 8)
        Wgt[(size_t)(n0 + r) * KG + si * HH + k0 + tx] = __float2half(t[tx][r]);
}

__global__ void bsum_k(const float* __restrict__ bo, float* __restrict__ bsum)
{
    int n = threadIdx.x;
    bsum[n] = 0.25f * (bo[n] + bo[HH + n] + bo[2 * HH + n]);
}

// =================== fp16 mma GEMM mainloop, tile 128x128, generic K ===================
#define OSTRIDE 36
#define GBUF (128 * OSTRIDE)
__device__ __forceinline__ void mma_mainloop(const __half* __restrict__ A, int bm, int lda,
                                             const __half* __restrict__ Bw, int bn, int ldb,
                                             int kdim, uint32_t* sbuf, float acc[2][8][4])
{
    const int tid  = threadIdx.x;
    const int warp = tid >> 5;
    const int lane = tid & 31;
    const int gid  = lane >> 2;
    const int tig  = lane & 3;
    const int wm = (warp & 3) * 32;
    const int wn = (warp >> 2) * 64;
    const uint32_t sb = (uint32_t)__cvta_generic_to_shared(sbuf);

    #pragma unroll
    for (int mt = 0; mt < 2; mt++)
        #pragma unroll
        for (int nt = 0; nt < 8; nt++)
            #pragma unroll
            for (int i = 0; i < 4; i++) acc[mt][nt][i] = 0.f;

    auto issue = [&](int kc, int st) {
        uint32_t aoff = sb + (uint32_t)(2 * st) * (GBUF * 4);
        uint32_t boff = aoff + GBUF * 4;
        for (int i = tid; i < 1024; i += 256) {
            int m = i >> 3, q = i & 7;
            uint32_t so = (uint32_t)(m * OSTRIDE + q * 4) * 4;
            cp16(aoff + so, &A[(size_t)(bm + m) * lda + kc + q * 8]);
            cp16(boff + so, &Bw[(size_t)(bn + m) * ldb + kc + q * 8]);
        }
        CP_COMMIT();
    };

    const int nchunks = kdim >> 6;
    issue(0, 0);
    for (int kci = 0; kci < nchunks; kci++) {
        const bool more = (kci + 1) < nchunks;
        if (more) issue((kci + 1) * 64, (kci + 1) & 1);
        if (more) CP_WAIT1(); else CP_WAIT0();
        __syncthreads();
        uint32_t* As = sbuf + 2 * (kci & 1) * GBUF;
        uint32_t* Bs = As + GBUF;
        #pragma unroll
        for (int ks = 0; ks < 4; ks++) {
            uint32_t a[2][4];
            #pragma unroll
            for (int mt = 0; mt < 2; mt++) {
                int r0 = (wm + mt * 16 + gid) * OSTRIDE + ks * 8;
                int r1 = (wm + mt * 16 + gid + 8) * OSTRIDE + ks * 8;
                a[mt][0] = As[r0 + tig];
                a[mt][1] = As[r1 + tig];
                a[mt][2] = As[r0 + tig + 4];
                a[mt][3] = As[r1 + tig + 4];
            }
            #pragma unroll
            for (int nt = 0; nt < 8; nt++) {
                int nr = (wn + nt * 8 + gid) * OSTRIDE + ks * 8;
                uint32_t b0 = Bs[nr + tig];
                uint32_t b1 = Bs[nr + tig + 4];
                #pragma unroll
                for (int mt = 0; mt < 2; mt++)
                    mma_f16(acc[mt][nt], a[mt], b0, b1);
            }
        }
        __syncthreads();
    }
}

// QKV mma GEMM: grid (18, 2, 9); z: si=z/3, which=z%3.
__global__ void __launch_bounds__(256)
gemm_qkv_mma_k(const __half* __restrict__ Xh, const __half* __restrict__ Wt,
               const float* __restrict__ bq, const float* __restrict__ bk,
               const float* __restrict__ bv,
               __half* __restrict__ Q, __half* __restrict__ K,
               uint32_t* __restrict__ Vt)
{
    __shared__ uint32_t sbuf[4 * GBUF];
    int z = blockIdx.z;
    int si = z / 3, which = z - si * 3;
    int bm = blockIdx.x * 128, bn = blockIdx.y * 128;

    float acc[2][8][4];
    mma_mainloop(Xh, bm, HH, Wt + (size_t)z * HH * HH, bn, HH, HH, sbuf, acc);

    const int tid  = threadIdx.x;
    const int warp = tid >> 5;
    const int lane = tid & 31;
    const int gid  = lane >> 2;
    const int tig  = lane & 3;
    const int wm = (warp & 3) * 32;
    const int wn = (warp >> 2) * 64;

    if (which < 2) {
        const float* bias = ((which == 0) ? bq : bk) + si * HH;
        __half* C = ((which == 0) ? Q : K) + (size_t)si * NELEM;
        float oscale = (which == 0) ? (0.17677669529663687f * 1.4426950408889634f) : 1.0f;
        #pragma unroll
        for (int nt = 0; nt < 8; nt++) {
            int n = bn + wn + nt * 8 + 2 * tig;
            float b0 = bias[n], b1 = bias[n + 1];
            #pragma unroll
            for (int mt = 0; mt < 2; mt++) {
                int m = bm + wm + mt * 16 + gid;
                *(uint32_t*)&C[(size_t)m * 256 + n] =
                    packh2((acc[mt][nt][0] + b0) * oscale, (acc[mt][nt][1] + b1) * oscale);
                *(uint32_t*)&C[(size_t)(m + 8) * 256 + n] =
                    packh2((acc[mt][nt][2] + b0) * oscale, (acc[mt][nt][3] + b1) * oscale);
            }
        }
    } else {
        // stage fp16 tile [tok][dim] in smem, then write transposed packed Vt
        const float* bias = bv + si * HH;
        __half* stag = (__half*)sbuf;            // [128 tok][stride 130]
        __syncthreads();
        #pragma unroll
        for (int nt = 0; nt < 8; nt++) {
            int nl = wn + nt * 8 + 2 * tig;
            float b0 = bias[bn + nl], b1 = bias[bn + nl + 1];
            #pragma unroll
            for (int mt = 0; mt < 2; mt++) {
                int ml = wm + mt * 16 + gid;
                *(uint32_t*)&stag[ml * 130 + nl] =
                    packh2(acc[mt][nt][0] + b0, acc[mt][nt][1] + b1);
                *(uint32_t*)&stag[(ml + 8) * 130 + nl] =
                    packh2(acc[mt][nt][2] + b0, acc[mt][nt][3] + b1);
            }
        }
        __syncthreads();
        const int tpg0 = bm >> 1;
        uint32_t* vtb = Vt + (size_t)si * 8 * 32 * TPAIRS;
        #pragma unroll
        for (int j = tid; j < 8192; j += 256) {
            int tp = j & 63;
            int nl = j >> 6;
            int ncol = bn + nl;
            int h = ncol >> 5, d = ncol & 31;
            __half lo = stag[(2 * tp) * 130 + nl];
            __half hi = stag[(2 * tp + 1) * 130 + nl];
            __half2 pr = __halves2half2(lo, hi);
            vtb[((size_t)(h * 32 + d)) * TPAIRS + tpg0 + tp] = *(uint32_t*)&pr;
        }
    }
}

// =================== pregather: overlap-add average (uint4 vectorized) ===================
// G[token][si*256+k] = (0.25/count) * sum_w attnh[row(w)][k]; 8 dims per thread
__global__ void __launch_bounds__(256)
pregather_k(const __half* __restrict__ attnh, __half* __restrict__ G)
{
    int idx = blockIdx.x * 256 + threadIdx.x;   // [0, 2304*96)
    int t = idx / 96;
    int rem = idx - t * 96;
    int si = rem >> 5;
    int quad = rem & 31;       // 8-dim group
    int f = t >> 7, pos = t & 127;

    const int sc[3] = {2, 4, 6};
    const int Ss[3] = {256, 512, 768};
    const int ro[3] = {ROFF0, ROFF1, ROFF2};
    int s = sc[si], S = Ss[si];
    int nw = F - s + 1;
    int wlo = max(0, f - s + 1);
    int whi = min(f, nw - 1);
    float a0 = 0.f, a1 = 0.f, a2 = 0.f, a3 = 0.f, a4 = 0.f, a5 = 0.f, a6 = 0.f, a7 = 0.f;
    for (int ww = wlo; ww <= whi; ww++) {
        int r = ro[si] + ww * S + (f - ww) * PP + pos;
        uint4 v = *(const uint4*)&attnh[(size_t)r * HH + quad * 8];
        float2 f0 = __half22float2(*(__half2*)&v.x);
        float2 f1 = __half22float2(*(__half2*)&v.y);
        float2 f2 = __half22float2(*(__half2*)&v.z);
        float2 f3 = __half22float2(*(__half2*)&v.w);
        a0 += f0.x; a1 += f0.y; a2 += f1.x; a3 += f1.y;
        a4 += f2.x; a5 += f2.y; a6 += f3.x; a7 += f3.y;
    }
    float wt = 0.25f / (float)(whi - wlo + 1);
    uint4 o;
    o.x = packh2(a0 * wt, a1 * wt);
    o.y = packh2(a2 * wt, a3 * wt);
    o.z = packh2(a4 * wt, a5 * wt);
    o.w = packh2(a6 * wt, a7 * wt);
    *(uint4*)&G[(size_t)t * KG + si * HH + quad * 8] = o;
}

// =================== gproj GEMM [2304x768]@[768x256] + fused colsum/X epilogue ===================
// grid (18, 2). Epilogue: v = acc + bsum; per-frame column sums -> vsum[iter];
// fp16 Xh write only when another iteration follows.
__global__ void __launch_bounds__(256)
gemm_gproj_mma_k(const __half* __restrict__ G, const __half* __restrict__ Wgt,
                 const float* __restrict__ bsum, float* __restrict__ vsum,
                 __half* __restrict__ Xh, int writeX)
{
    __shared__ uint32_t sbuf[4 * GBUF];
    int bm = blockIdx.x * 128, bn = blockIdx.y * 128;

    float acc[2][8][4];
    mma_mainloop(G, bm, KG, Wgt, bn, KG, KG, sbuf, acc);

    const int tid  = threadIdx.x;
    const int warp = tid >> 5;
    const int lane = tid & 31;
    const int gid  = lane >> 2;
    const int tig  = lane & 3;
    const int wm = (warp & 3) * 32;
    const int wn = (warp >> 2) * 64;
    const int f = bm >> 7;             // one frame per 128-row tile
    float* vs = vsum + f * HH;

    #pragma unroll
    for (int nt = 0; nt < 8; nt++) {
        int n = bn + wn + nt * 8 + 2 * tig;
        float b0 = bsum[n], b1 = bsum[n + 1];
        // column sums over this warp's 32 rows (excl. bias; added in classify)
        float s0 = acc[0][nt][0] + acc[0][nt][2] + acc[1][nt][0] + acc[1][nt][2];
        float s1 = acc[0][nt][1] + acc[0][nt][3] + acc[1][nt][1] + acc[1][nt][3];
        #pragma unroll
        for (int off = 4; off < 32; off <<= 1) {
            s0 += __shfl_xor_sync(0xffffffffu, s0, off);
            s1 += __shfl_xor_sync(0xffffffffu, s1, off);
        }
        if (gid == 0) {
            atomicAdd(&vs[n], s0);
            atomicAdd(&vs[n + 1], s1);
        }
        if (writeX) {
            #pragma unroll
            for (int mt = 0; mt < 2; mt++) {
                int m = bm + wm + mt * 16 + gid;
                *(uint32_t*)&Xh[(size_t)m * 256 + n] =
                    packh2(acc[mt][nt][0] + b0, acc[mt][nt][1] + b1);
                *(uint32_t*)&Xh[(size_t)(m + 8) * 256 + n] =
                    packh2(acc[mt][nt][2] + b0, acc[mt][nt][3] + b1);
            }
        }
    }
}

// =================== tensor-core flash attention, hd=32, all fp16 mma ===================
#define KPSTRIDE 36
#define VTSTRIDE 36
__global__ void __launch_bounds__(256, 3)
attn_mma_k(const __half* __restrict__ Qg, const __half* __restrict__ Kg,
           const uint32_t* __restrict__ Vt, __half* __restrict__ O)
{
    __shared__ uint32_t Kp[2][64 * KPSTRIDE];   // [stage][key][kpair]
    __shared__ uint32_t Vs[2][32 * VTSTRIDE];   // [stage][dim][keypair]

    const int tid  = threadIdx.x;
    const int warp = tid >> 5;
    const int lane = tid & 31;
    const int gid  = lane >> 2;
    const int tig  = lane & 3;
    const int h    = blockIdx.y;

    int pid = blockIdx.x;
    int si, S, w, j0, rowoff;
    if (pid < 78)       { si = 2; S = 768; w = pid / 6;  j0 = (pid - w * 6) << 7; rowoff = ROFF2; }
    else if (pid < 138) { pid -= 78;  si = 1; S = 512; w = pid >> 2; j0 = (pid & 3) << 7; rowoff = ROFF1; }
    else                { pid -= 138; si = 0; S = 256; w = pid >> 1; j0 = (pid & 1) << 7; rowoff = ROFF0; }

    const __half* Q = Qg + (size_t)si * NELEM;
    const __half* K = Kg + (size_t)si * NELEM;
    const uint32_t* Vtb = Vt + ((size_t)si * 8 + h) * 32 * TPAIRS;

    const uint32_t kpb = (uint32_t)__cvta_generic_to_shared(&Kp[0][0]);
    const uint32_t vsb = (uint32_t)__cvta_generic_to_shared(&Vs[0][0]);

    auto issueKV = [&](int kb, int st) {
        {
            const __half* kg = K + ((size_t)(w * PP + kb)) * HH + h * 32;
            int key = tid >> 2, q = tid & 3;
            cp16(kpb + (uint32_t)(st * 64 * KPSTRIDE + key * KPSTRIDE + q * 4) * 4,
                 kg + (size_t)key * HH + q * 8);
        }
        {
            const uint32_t* vg = Vtb + ((w * PP + kb) >> 1);
            int d = tid >> 3, q = tid & 7;
            cp16(vsb + (uint32_t)(st * 32 * VTSTRIDE + d * VTSTRIDE + q * 4) * 4,
                 vg + (size_t)d * TPAIRS + q * 4);
        }
        CP_COMMIT();
    };

    const int qrow = w * PP + j0 + warp * 16 + gid;
    uint32_t qa[2][4];
    #pragma unroll
    for (int ks = 0; ks < 2; ks++) {
        const uint32_t* q0 = (const uint32_t*)(Q + (size_t)qrow * HH + h * 32 + ks * 16);
        const uint32_t* q1 = (const uint32_t*)(Q + (size_t)(qrow + 8) * HH + h * 32 + ks * 16);
        qa[ks][0] = q0[tig];
        qa[ks][1] = q1[tig];
        qa[ks][2] = q0[tig + 4];
        qa[ks][3] = q1[tig + 4];
    }

    float o[4][4];
    #pragma unroll
    for (int v = 0; v < 4; v++)
        #pragma unroll
        for (int i = 0; i < 4; i++) o[v][i] = 0.f;
    float l0 = 0.f, l1 = 0.f;

    issueKV(0, 0);
    for (int kb = 0; kb < S; kb += 64) {
        const int st = (kb >> 6) & 1;
        const bool more = (kb + 64) < S;
        if (more) issueKV(kb + 64, st ^ 1);
        if (more) CP_WAIT1(); else CP_WAIT0();
        __syncthreads();

        float s[8][4];
        #pragma unroll
        for (int t = 0; t < 8; t++) {
            s[t][0] = s[t][1] = s[t][2] = s[t][3] = 0.f;
            const int krow = (8 * t + gid) * KPSTRIDE;
            #pragma unroll
            for (int ks = 0; ks < 2; ks++) {
                uint32_t b0 = Kp[st][krow + ks * 8 + tig];
                uint32_t b1 = Kp[st][krow + ks * 8 + tig + 4];
                mma_f16(s[t], qa[ks], b0, b1);
            }
        }

        uint32_t e0[8], e1[8];
        #pragma unroll
        for (int t = 0; t < 8; t++) {
            e0[t] = h2ex2(packh2(s[t][0], s[t][1]));
            e1[t] = h2ex2(packh2(s[t][2], s[t][3]));
            float2 f0 = __half22float2(*(__half2*)&e0[t]);
            float2 f1 = __half22float2(*(__half2*)&e1[t]);
            l0 += f0.x + f0.y;
            l1 += f1.x + f1.y;
        }

        #pragma unroll
        for (int u = 0; u < 4; u++) {
            uint32_t pa[4];
            pa[0] = e0[2*u];
            pa[1] = e1[2*u];
            pa[2] = e0[2*u+1];
            pa[3] = e1[2*u+1];
            #pragma unroll
            for (int v = 0; v < 4; v++) {
                uint32_t b0 = Vs[st][(gid + 8 * v) * VTSTRIDE + 8 * u + tig];
                uint32_t b1 = Vs[st][(gid + 8 * v) * VTSTRIDE + 8 * u + tig + 4];
                mma_f16(o[v], pa, b0, b1);
            }
        }
        __syncthreads();
    }

    l0 += __shfl_xor_sync(0xffffffffu, l0, 1);
    l0 += __shfl_xor_sync(0xffffffffu, l0, 2);
    l1 += __shfl_xor_sync(0xffffffffu, l1, 1);
    l1 += __shfl_xor_sync(0xffffffffu, l1, 2);
    float il0 = 1.f / l0, il1 = 1.f / l1;

    const int orow = rowoff + w * S + j0 + warp * 16 + gid;
    #pragma unroll
    for (int v = 0; v < 4; v++) {
        *(uint32_t*)&O[(size_t)orow * HH + h * 32 + v * 8 + 2 * tig] =
            packh2(o[v][0] * il0, o[v][1] * il0);
        *(uint32_t*)&O[(size_t)(orow + 8) * HH + h * 32 + v * 8 + 2 * tig] =
            packh2(o[v][2] * il1, o[v][3] * il1);
    }
}

// =================== classifier (combines per-iter colsums) ===================
__global__ void classify_k(const float* __restrict__ vsum, const float* __restrict__ warr,
                           const float* __restrict__ bsum,
                           const float* __restrict__ clsW, const float* __restrict__ clsb,
                           float* __restrict__ out)
{
    __shared__ float cs[HH];
    int tid = threadIdx.x;        // 128
    for (int h = tid; h < HH; h += 128) {
        float s = 0.f;
        float bb = 128.f * bsum[h];
        #pragma unroll
        for (int f = 0; f < F; f++) {
            float w0 = warr[f], w1 = warr[F + f];
            float v0 = vsum[f * HH + h] + bb;
            float v1 = vsum[F * HH + f * HH + h] + bb;
            s += w1 * v1 + (1.f - w1) * w0 * v0;
        }
        cs[h] = s;
    }
    __syncthreads();
    int j = blockIdx.x * 128 + tid;
    if (j < NCLS) {
        float acc = clsb[j];
        for (int h = 0; h < HH; h++) acc = fmaf(cs[h], clsW[h * NCLS + j], acc);
        out[j] = acc;
    }
}

// =================== host launch ===================
extern "C" void kernel_launch(void* const* d_in, const int* in_sizes, int n_in,
                              void* d_out, int out_size)
{
    (void)in_sizes; (void)n_in; (void)out_size;
    const float* embed  = (const float*)d_in[0];
    const float* halt_W = (const float*)d_in[3];
    const float* halt_b = (const float*)d_in[4];
    const float* cls_W  = (const float*)d_in[8];
    const float* cls_b  = (const float*)d_in[9];
    const float* Wq = (const float*)d_in[10];
    const float* bq = (const float*)d_in[11];
    const float* Wk = (const float*)d_in[12];
    const float* bk = (const float*)d_in[13];
    const float* Wv = (const float*)d_in[14];
    const float* bv = (const float*)d_in[15];
    const float* Wo = (const float*)d_in[16];
    const float* bo = (const float*)d_in[17];
    float* out = (float*)d_out;

    float *sig, *ptn, *Rt, *warr, *bsum, *vsum;
    __half *Xh, *Qh, *Kh, *attnh, *G, *Wqkvh, *Wgt;
    uint32_t *Vt;
    cudaGetSymbolAddress((void**)&Xh,      d_Xh);
    cudaGetSymbolAddress((void**)&Qh,      d_Qh);
    cudaGetSymbolAddress((void**)&Kh,      d_Kh);
    cudaGetSymbolAddress((void**)&Vt,      d_Vt);
    cudaGetSymbolAddress((void**)&attnh,   d_attnh);
    cudaGetSymbolAddress((void**)&G,       d_G);
    cudaGetSymbolAddress((void**)&Wqkvh,   d_Wqkvh);
    cudaGetSymbolAddress((void**)&Wgt,     d_Wgt);
    cudaGetSymbolAddress((void**)&bsum,    d_bsum);
    cudaGetSymbolAddress((void**)&vsum,    d_vsum);
    cudaGetSymbolAddress((void**)&sig,     d_sig);
    cudaGetSymbolAddress((void**)&ptn,     d_ptn);
    cudaGetSymbolAddress((void**)&Rt,      d_Rt);
    cudaGetSymbolAddress((void**)&warr,    d_warr);

    // weight conversions (once per call)
    {
        dim3 b(32, 8);
        dim3 gq(8, 8, 9);
        convwt_qkv_k<<<gq, b>>>(Wq, Wk, Wv, Wqkvh);
        dim3 gg(8, 8, 3);
        convwt_gproj_k<<<gg, b>>>(Wo, Wgt);
        bsum_k<<<1, 256>>>(bo, bsum);
    }
    // iter-0 halting + fp16 X conversion (fused)
    halt_sig_k<<<TPAIRS / 8, 256>>>(embed, halt_W, halt_b, sig, Xh);

    for (int iter = 0; iter < 2; iter++) {
        act2_k<<<1, 576>>>(sig, ptn, Rt, warr, vsum, iter);

        // QKV (fp16 tensor GEMM) for all 3 scales; V written transposed (Vt)
        dim3 gq(NTOK / 128, 2, 9);
        gemm_qkv_mma_k<<<gq, 256>>>(Xh, Wqkvh, bq, bk, bv, Qh, Kh, Vt);

        // tensor-core attention, all scales: 172 pairs x 8 heads, 128 q/block
        dim3 ga(172, 8);
        attn_mma_k<<<ga, 256>>>(Qh, Kh, Vt, attnh);

        // overlap-add average of attn rows (before projection; linearity)
        pregather_k<<<(NTOK * 96) / 256, 256>>>(attnh, G);

        // fused projection GEMM + per-frame colsum (+Xh for next iter)
        dim3 gg(NTOK / 128, 2);
        gemm_gproj_mma_k<<<gg, 256>>>(G, Wgt, bsum, vsum + iter * F * HH, Xh,
                                      iter == 0 ? 1 : 0);

        // halting sigmoid for next iteration (reads fp16 Xh)
        if (iter == 0)
            halt_sig_h_k<<<TPAIRS / 8, 256>>>(Xh, halt_W, halt_b, sig);
    }
    classify_k<<<(NCLS + 127) / 128, 128>>>(vsum, warr, bsum, cls_W, cls_b, out);
}

// round 14
// speedup vs baseline: 1.2227x; 1.1200x over previous
#include <cuda_runtime.h>
#include <cuda_fp16.h>
#include <math.h>
#include <stdint.h>

// Problem constants
#define F 18
#define PP 128
#define HH 256
#define NCLS 625
#define NTOK (F*PP)            // 2304
#define NELEM (F*PP*HH)        // 589824
#define TPAIRS 1152            // NTOK/2
#define KG 768                 // gproj K dimension (3 scales x 256)
// frame-pair slot bases/strides: s2 (3 slots), s4 (7), s6 (11)
#define SBASE0 0
#define SBASE1 54
#define SBASE2 180
#define NSLOTS 378

// -------- device scratch (allocation-free) --------
__device__ __half d_Xh[NELEM];             // fp16 inputs (for QKV mma)
__device__ __half d_Qh[3*NELEM];
__device__ __half d_Kh[3*NELEM];
__device__ uint32_t d_Vt[3*8*32*TPAIRS];   // [si][h][dim][tokpair] packed half2
__device__ __half d_Nbuf[(size_t)NSLOTS*128*256];  // unnormalized PV per frame-pair
__device__ float d_Dbuf[(size_t)NSLOTS*128*8];     // exp-sums per frame-pair [slot][q][h]
__device__ __half d_G[NTOK*KG];            // combined attn [token][si*256+k] fp16
__device__ __half d_Wqkvh[9*HH*HH];        // QKV weights transposed [si*3+which][n][k] fp16
__device__ __half d_Wgt[HH*KG];            // gproj weights [n][si*256+k] fp16
__device__ float d_bsum[HH];               // 0.25*(bo0+bo1+bo2)
__device__ float d_vsum[2*F*HH];           // per-iter per-frame column sums of gproj acc
__device__ float d_sig[NTOK];
__device__ float d_ptn[F];
__device__ float d_Rt[F];
__device__ float d_warr[2*F];

__device__ __forceinline__ uint32_t packh2(float a, float b) {
    __half2 h = __floats2half2_rn(a, b);
    return *(uint32_t*)&h;
}

__device__ __forceinline__ uint32_t h2ex2(uint32_t x) {
    uint32_t y;
    asm("ex2.approx.f16x2 %0, %1;" : "=r"(y) : "r"(x));
    return y;
}

__device__ __forceinline__ void cp16(uint32_t saddr, const void* g) {
    asm volatile("cp.async.cg.shared.global [%0], [%1], 16;\n" :: "r"(saddr), "l"(g));
}
#define CP_COMMIT() asm volatile("cp.async.commit_group;\n" ::: "memory")
#define CP_WAIT1()  asm volatile("cp.async.wait_group 1;\n" ::: "memory")
#define CP_WAIT0()  asm volatile("cp.async.wait_group 0;\n" ::: "memory")

// mma.sync m16n8k16 fp16 -> fp32 accumulate in-place
__device__ __forceinline__ void mma_f16(float c[4], const uint32_t a[4],
                                        uint32_t b0, uint32_t b1)
{
    asm volatile(
        "mma.sync.aligned.m16n8k16.row.col.f32.f16.f16.f32 "
        "{%0,%1,%2,%3}, {%4,%5,%6,%7}, {%8,%9}, {%0,%1,%2,%3};\n"
        : "+f"(c[0]), "+f"(c[1]), "+f"(c[2]), "+f"(c[3])
        : "r"(a[0]), "r"(a[1]), "r"(a[2]), "r"(a[3]), "r"(b0), "r"(b1));
}

// =================== iter-0 halting + X->fp16 (fused) ===================
__global__ void __launch_bounds__(256)
halt_sig_k(const float* __restrict__ x, const float* __restrict__ hW,
           const float* __restrict__ hb, float* __restrict__ sig,
           __half* __restrict__ Xh)
{
    int warp = threadIdx.x >> 5;
    int lane = threadIdx.x & 31;
    int pos = blockIdx.x * 8 + warp;
    const float* xp0 = x + (size_t)pos * HH + lane * 8;
    const float* xp1 = x + (size_t)(pos + TPAIRS) * HH + lane * 8;
    const float* wp = hW + lane * 8;
    float4 a0 = *(const float4*)xp0;
    float4 a1 = *(const float4*)(xp0 + 4);
    float4 b0 = *(const float4*)xp1;
    float4 b1 = *(const float4*)(xp1 + 4);
    float4 w0 = *(const float4*)wp;
    float4 w1 = *(const float4*)(wp + 4);
    uint4 ha, hb4;
    ha.x = packh2(a0.x, a0.y);  ha.y = packh2(a0.z, a0.w);
    ha.z = packh2(a1.x, a1.y);  ha.w = packh2(a1.z, a1.w);
    hb4.x = packh2(b0.x, b0.y); hb4.y = packh2(b0.z, b0.w);
    hb4.z = packh2(b1.x, b1.y); hb4.w = packh2(b1.z, b1.w);
    *(uint4*)&Xh[(size_t)pos * HH + lane * 8] = ha;
    *(uint4*)&Xh[(size_t)(pos + TPAIRS) * HH + lane * 8] = hb4;

    float acc0 = a0.x * w0.x + a0.y * w0.y + a0.z * w0.z + a0.w * w0.w
               + a1.x * w1.x + a1.y * w1.y + a1.z * w1.z + a1.w * w1.w;
    float acc1 = b0.x * w0.x + b0.y * w0.y + b0.z * w0.z + b0.w * w0.w
               + b1.x * w1.x + b1.y * w1.y + b1.z * w1.z + b1.w * w1.w;
    #pragma unroll
    for (int off = 16; off > 0; off >>= 1) {
        acc0 += __shfl_xor_sync(0xffffffffu, acc0, off);
        acc1 += __shfl_xor_sync(0xffffffffu, acc1, off);
    }
    if (lane == 0) {
        sig[pos] = 1.f / (1.f + __expf(-(acc0 + hb[0])));
        sig[pos + TPAIRS] = 1.f / (1.f + __expf(-(acc1 + hb[0])));
    }
}

// =================== iter-1 halting (fp16 Xh) ===================
__global__ void __launch_bounds__(256)
halt_sig_h_k(const __half* __restrict__ Xh, const float* __restrict__ hW,
             const float* __restrict__ hb, float* __restrict__ sig)
{
    int warp = threadIdx.x >> 5;
    int lane = threadIdx.x & 31;
    int pos = blockIdx.x * 8 + warp;
    const uint32_t* x0 = (const uint32_t*)(Xh + (size_t)pos * HH) + lane * 4;
    const uint32_t* x1 = (const uint32_t*)(Xh + (size_t)(pos + TPAIRS) * HH) + lane * 4;
    const float* wp = hW + lane * 8;
    float acc0 = 0.f, acc1 = 0.f;
    #pragma unroll
    for (int j = 0; j < 4; j++) {
        uint32_t u0 = x0[j], u1 = x1[j];
        float2 a = __half22float2(*(__half2*)&u0);
        float2 b = __half22float2(*(__half2*)&u1);
        acc0 += a.x * wp[2*j] + a.y * wp[2*j+1];
        acc1 += b.x * wp[2*j] + b.y * wp[2*j+1];
    }
    #pragma unroll
    for (int off = 16; off > 0; off >>= 1) {
        acc0 += __shfl_xor_sync(0xffffffffu, acc0, off);
        acc1 += __shfl_xor_sync(0xffffffffu, acc1, off);
    }
    if (lane == 0) {
        sig[pos] = 1.f / (1.f + __expf(-(acc0 + hb[0])));
        sig[pos + TPAIRS] = 1.f / (1.f + __expf(-(acc1 + hb[0])));
    }
}

// =================== halting phase 2 (mean) + ACT + vsum zero ===================
__global__ void __launch_bounds__(576)
act2_k(const float* __restrict__ sig, float* __restrict__ ptn,
       float* __restrict__ Rt, float* __restrict__ warr,
       float* __restrict__ vsum, int iter)
{
    for (int i = threadIdx.x; i < F * HH; i += 576)
        vsum[iter * F * HH + i] = 0.f;

    int f = threadIdx.x >> 5;
    int lane = threadIdx.x & 31;
    const float4 v = *(const float4*)&sig[f * PP + lane * 4];
    float acc = v.x + v.y + v.z + v.w;
    #pragma unroll
    for (int off = 16; off > 0; off >>= 1)
        acc += __shfl_xor_sync(0xffffffffu, acc, off);
    if (lane == 0 && f < F) {
        float pf = acc * (1.f / 128.f);
        float pt = iter == 0 ? 0.f : ptn[f];
        float rt = iter == 0 ? 0.f : Rt[f];
        float run = (pt < 1.0f) ? 1.f : 0.f;
        float t = pt + pf * run;
        float nh   = (t > 0.99f)  ? run : 0.f;
        float run2 = (t <= 0.99f) ? run : 0.f;
        pt = pt + pf * run2;
        rt = rt + nh * (1.f - pt);
        pt = pt + nh * rt;
        ptn[f] = pt; Rt[f] = rt;
        warr[iter * F + f] = pf * run2 + nh * rt;
    }
}

// =================== weight conversions ===================
__global__ void __launch_bounds__(256)
convwt_qkv_k(const float* __restrict__ Wq, const float* __restrict__ Wk,
             const float* __restrict__ Wv, __half* __restrict__ Wt)
{
    __shared__ float t[32][33];
    int z = blockIdx.z;
    int si = z / 3, which = z - si * 3;
    const float* W = (which == 0) ? Wq : ((which == 1) ? Wk : Wv);
    const float* src = W + (size_t)si * HH * HH;
    __half* dst = Wt + (size_t)z * HH * HH;
    int k0 = blockIdx.x * 32, n0 = blockIdx.y * 32;
    int tx = threadIdx.x, ty = threadIdx.y;
    #pragma unroll
    for (int r = ty; r < 32; r += 8)
        t[r][tx] = src[(size_t)(k0 + r) * HH + n0 + tx];
    __syncthreads();
    #pragma unroll
    for (int r = ty; r < 32; r += 8)
        dst[(size_t)(n0 + r) * HH + k0 + tx] = __float2half(t[tx][r]);
}

__global__ void __launch_bounds__(256)
convwt_gproj_k(const float* __restrict__ Wo, __half* __restrict__ Wgt)
{
    __shared__ float t[32][33];
    int si = blockIdx.z;
    const float* src = Wo + (size_t)si * HH * HH;
    int k0 = blockIdx.x * 32, n0 = blockIdx.y * 32;
    int tx = threadIdx.x, ty = threadIdx.y;
    #pragma unroll
    for (int r = ty; r < 32; r += 8)
        t[r][tx] = src[(size_t)(k0 + r) * HH + n0 + tx];
    __syncthreads();
    #pragma unroll
    for (int r = ty; r < 32; r += 8)
        Wgt[(size_t)(n0 + r) * KG + si * HH + k0 + tx] = __float2half(t[tx][r]);
}

__global__ void bsum_k(const float* __restrict__ bo, float* __restrict__ bsum)
{
    int n = threadIdx.x;
    bsum[n] = 0.25f * (bo[n] + bo[HH + n] + bo[2 * HH + n]);
}

// =================== fp16 mma GEMM mainloop, tile 128x128, generic K ===================
#define OSTRIDE 36
#define GBUF (128 * OSTRIDE)
__device__ __forceinline__ void mma_mainloop(const __half* __restrict__ A, int bm, int lda,
                                             const __half* __restrict__ Bw, int bn, int ldb,
                                             int kdim, uint32_t* sbuf, float acc[2][8][4])
{
    const int tid  = threadIdx.x;
    const int warp = tid >> 5;
    const int lane = tid & 31;
    const int gid  = lane >> 2;
    const int tig  = lane & 3;
    const int wm = (warp & 3) * 32;
    const int wn = (warp >> 2) * 64;
    const uint32_t sb = (uint32_t)__cvta_generic_to_shared(sbuf);

    #pragma unroll
    for (int mt = 0; mt < 2; mt++)
        #pragma unroll
        for (int nt = 0; nt < 8; nt++)
            #pragma unroll
            for (int i = 0; i < 4; i++) acc[mt][nt][i] = 0.f;

    auto issue = [&](int kc, int st) {
        uint32_t aoff = sb + (uint32_t)(2 * st) * (GBUF * 4);
        uint32_t boff = aoff + GBUF * 4;
        for (int i = tid; i < 1024; i += 256) {
            int m = i >> 3, q = i & 7;
            uint32_t so = (uint32_t)(m * OSTRIDE + q * 4) * 4;
            cp16(aoff + so, &A[(size_t)(bm + m) * lda + kc + q * 8]);
            cp16(boff + so, &Bw[(size_t)(bn + m) * ldb + kc + q * 8]);
        }
        CP_COMMIT();
    };

    const int nchunks = kdim >> 6;
    issue(0, 0);
    for (int kci = 0; kci < nchunks; kci++) {
        const bool more = (kci + 1) < nchunks;
        if (more) issue((kci + 1) * 64, (kci + 1) & 1);
        if (more) CP_WAIT1(); else CP_WAIT0();
        __syncthreads();
        uint32_t* As = sbuf + 2 * (kci & 1) * GBUF;
        uint32_t* Bs = As + GBUF;
        #pragma unroll
        for (int ks = 0; ks < 4; ks++) {
            uint32_t a[2][4];
            #pragma unroll
            for (int mt = 0; mt < 2; mt++) {
                int r0 = (wm + mt * 16 + gid) * OSTRIDE + ks * 8;
                int r1 = (wm + mt * 16 + gid + 8) * OSTRIDE + ks * 8;
                a[mt][0] = As[r0 + tig];
                a[mt][1] = As[r1 + tig];
                a[mt][2] = As[r0 + tig + 4];
                a[mt][3] = As[r1 + tig + 4];
            }
            #pragma unroll
            for (int nt = 0; nt < 8; nt++) {
                int nr = (wn + nt * 8 + gid) * OSTRIDE + ks * 8;
                uint32_t b0 = Bs[nr + tig];
                uint32_t b1 = Bs[nr + tig + 4];
                #pragma unroll
                for (int mt = 0; mt < 2; mt++)
                    mma_f16(acc[mt][nt], a[mt], b0, b1);
            }
        }
        __syncthreads();
    }
}

// QKV mma GEMM: grid (18, 2, 9); z: si=z/3, which=z%3.
__global__ void __launch_bounds__(256)
gemm_qkv_mma_k(const __half* __restrict__ Xh, const __half* __restrict__ Wt,
               const float* __restrict__ bq, const float* __restrict__ bk,
               const float* __restrict__ bv,
               __half* __restrict__ Q, __half* __restrict__ K,
               uint32_t* __restrict__ Vt)
{
    __shared__ uint32_t sbuf[4 * GBUF];
    int z = blockIdx.z;
    int si = z / 3, which = z - si * 3;
    int bm = blockIdx.x * 128, bn = blockIdx.y * 128;

    float acc[2][8][4];
    mma_mainloop(Xh, bm, HH, Wt + (size_t)z * HH * HH, bn, HH, HH, sbuf, acc);

    const int tid  = threadIdx.x;
    const int warp = tid >> 5;
    const int lane = tid & 31;
    const int gid  = lane >> 2;
    const int tig  = lane & 3;
    const int wm = (warp & 3) * 32;
    const int wn = (warp >> 2) * 64;

    if (which < 2) {
        const float* bias = ((which == 0) ? bq : bk) + si * HH;
        __half* C = ((which == 0) ? Q : K) + (size_t)si * NELEM;
        float oscale = (which == 0) ? (0.17677669529663687f * 1.4426950408889634f) : 1.0f;
        #pragma unroll
        for (int nt = 0; nt < 8; nt++) {
            int n = bn + wn + nt * 8 + 2 * tig;
            float b0 = bias[n], b1 = bias[n + 1];
            #pragma unroll
            for (int mt = 0; mt < 2; mt++) {
                int m = bm + wm + mt * 16 + gid;
                *(uint32_t*)&C[(size_t)m * 256 + n] =
                    packh2((acc[mt][nt][0] + b0) * oscale, (acc[mt][nt][1] + b1) * oscale);
                *(uint32_t*)&C[(size_t)(m + 8) * 256 + n] =
                    packh2((acc[mt][nt][2] + b0) * oscale, (acc[mt][nt][3] + b1) * oscale);
            }
        }
    } else {
        const float* bias = bv + si * HH;
        __half* stag = (__half*)sbuf;            // [128 tok][stride 130]
        __syncthreads();
        #pragma unroll
        for (int nt = 0; nt < 8; nt++) {
            int nl = wn + nt * 8 + 2 * tig;
            float b0 = bias[bn + nl], b1 = bias[bn + nl + 1];
            #pragma unroll
            for (int mt = 0; mt < 2; mt++) {
                int ml = wm + mt * 16 + gid;
                *(uint32_t*)&stag[ml * 130 + nl] =
                    packh2(acc[mt][nt][0] + b0, acc[mt][nt][1] + b1);
                *(uint32_t*)&stag[(ml + 8) * 130 + nl] =
                    packh2(acc[mt][nt][2] + b0, acc[mt][nt][3] + b1);
            }
        }
        __syncthreads();
        const int tpg0 = bm >> 1;
        uint32_t* vtb = Vt + (size_t)si * 8 * 32 * TPAIRS;
        #pragma unroll
        for (int j = tid; j < 8192; j += 256) {
            int tp = j & 63;
            int nl = j >> 6;
            int ncol = bn + nl;
            int h = ncol >> 5, d = ncol & 31;
            __half lo = stag[(2 * tp) * 130 + nl];
            __half hi = stag[(2 * tp + 1) * 130 + nl];
            __half2 pr = __halves2half2(lo, hi);
            vtb[((size_t)(h * 32 + d)) * TPAIRS + tpg0 + tp] = *(uint32_t*)&pr;
        }
    }
}

// =================== frame-pair attention: N/D decomposition ===================
// Block = one (scale, query-frame, key-frame, head): 128 q x 128 k, hd=32.
// Writes UNNORMALIZED PV sums (N, fp16) and exp-sums (D, fp32) per frame pair.
// grid.x = 378 packed (si,fq,d) slots (invalid fk early-exit), grid.y = 8 heads.
#define KPSTRIDE 36
#define VTSTRIDE 36
__global__ void __launch_bounds__(256, 3)
attn_nd_k(const __half* __restrict__ Qg, const __half* __restrict__ Kg,
          const uint32_t* __restrict__ Vt, __half* __restrict__ Nbuf,
          float* __restrict__ Dbuf)
{
    __shared__ uint32_t Kp[2][64 * KPSTRIDE];
    __shared__ uint32_t Vs[2][32 * VTSTRIDE];

    int pid = blockIdx.x;
    int si, fq, d, slot, s;
    if (pid < 198)      { si = 2; s = 6; fq = pid / 11; d = pid - fq * 11; slot = SBASE2 + fq * 11 + d; }
    else if (pid < 324) { pid -= 198; si = 1; s = 4; fq = pid / 7; d = pid - fq * 7; slot = SBASE1 + fq * 7 + d; }
    else                { pid -= 324; si = 0; s = 2; fq = pid / 3; d = pid - fq * 3; slot = SBASE0 + fq * 3 + d; }
    const int fk = fq + d - (s - 1);
    if (fk < 0 || fk > 17) return;

    const int tid  = threadIdx.x;
    const int warp = tid >> 5;
    const int lane = tid & 31;
    const int gid  = lane >> 2;
    const int tig  = lane & 3;
    const int h    = blockIdx.y;

    const __half* Q = Qg + (size_t)si * NELEM;
    const __half* K = Kg + (size_t)si * NELEM;
    const uint32_t* Vtb = Vt + ((size_t)si * 8 + h) * 32 * TPAIRS;

    const uint32_t kpb = (uint32_t)__cvta_generic_to_shared(&Kp[0][0]);
    const uint32_t vsb = (uint32_t)__cvta_generic_to_shared(&Vs[0][0]);

    auto issueKV = [&](int kb, int st) {
        {
            const __half* kg = K + ((size_t)(fk * PP + kb)) * HH + h * 32;
            int key = tid >> 2, q = tid & 3;
            cp16(kpb + (uint32_t)(st * 64 * KPSTRIDE + key * KPSTRIDE + q * 4) * 4,
                 kg + (size_t)key * HH + q * 8);
        }
        {
            const uint32_t* vg = Vtb + ((fk * PP + kb) >> 1);
            int dd = tid >> 3, q = tid & 7;
            cp16(vsb + (uint32_t)(st * 32 * VTSTRIDE + dd * VTSTRIDE + q * 4) * 4,
                 vg + (size_t)dd * TPAIRS + q * 4);
        }
        CP_COMMIT();
    };

    const int qloc = warp * 16 + gid;
    const int qrow = fq * PP + qloc;
    uint32_t qa[2][4];
    #pragma unroll
    for (int ks = 0; ks < 2; ks++) {
        const uint32_t* q0 = (const uint32_t*)(Q + (size_t)qrow * HH + h * 32 + ks * 16);
        const uint32_t* q1 = (const uint32_t*)(Q + (size_t)(qrow + 8) * HH + h * 32 + ks * 16);
        qa[ks][0] = q0[tig];
        qa[ks][1] = q1[tig];
        qa[ks][2] = q0[tig + 4];
        qa[ks][3] = q1[tig + 4];
    }

    float o[4][4];
    #pragma unroll
    for (int v = 0; v < 4; v++)
        #pragma unroll
        for (int i = 0; i < 4; i++) o[v][i] = 0.f;
    float l0 = 0.f, l1 = 0.f;

    issueKV(0, 0);
    #pragma unroll
    for (int kt = 0; kt < 2; kt++) {
        if (kt == 0) { issueKV(64, 1); CP_WAIT1(); } else { CP_WAIT0(); }
        __syncthreads();

        float sc[8][4];
        #pragma unroll
        for (int t = 0; t < 8; t++) {
            sc[t][0] = sc[t][1] = sc[t][2] = sc[t][3] = 0.f;
            const int krow = (8 * t + gid) * KPSTRIDE;
            #pragma unroll
            for (int ks = 0; ks < 2; ks++) {
                uint32_t b0 = Kp[kt][krow + ks * 8 + tig];
                uint32_t b1 = Kp[kt][krow + ks * 8 + tig + 4];
                mma_f16(sc[t], qa[ks], b0, b1);
            }
        }

        uint32_t e0[8], e1[8];
        #pragma unroll
        for (int t = 0; t < 8; t++) {
            e0[t] = h2ex2(packh2(sc[t][0], sc[t][1]));
            e1[t] = h2ex2(packh2(sc[t][2], sc[t][3]));
            float2 f0 = __half22float2(*(__half2*)&e0[t]);
            float2 f1 = __half22float2(*(__half2*)&e1[t]);
            l0 += f0.x + f0.y;
            l1 += f1.x + f1.y;
        }

        #pragma unroll
        for (int u = 0; u < 4; u++) {
            uint32_t pa[4];
            pa[0] = e0[2*u];
            pa[1] = e1[2*u];
            pa[2] = e0[2*u+1];
            pa[3] = e1[2*u+1];
            #pragma unroll
            for (int v = 0; v < 4; v++) {
                uint32_t b0 = Vs[kt][(gid + 8 * v) * VTSTRIDE + 8 * u + tig];
                uint32_t b1 = Vs[kt][(gid + 8 * v) * VTSTRIDE + 8 * u + tig + 4];
                mma_f16(o[v], pa, b0, b1);
            }
        }
        __syncthreads();
    }

    l0 += __shfl_xor_sync(0xffffffffu, l0, 1);
    l0 += __shfl_xor_sync(0xffffffffu, l0, 2);
    l1 += __shfl_xor_sync(0xffffffffu, l1, 1);
    l1 += __shfl_xor_sync(0xffffffffu, l1, 2);

    __half* Nb = Nbuf + ((size_t)slot * 128) * 256 + h * 32;
    #pragma unroll
    for (int v = 0; v < 4; v++) {
        *(uint32_t*)&Nb[(size_t)qloc * 256 + v * 8 + 2 * tig] = packh2(o[v][0], o[v][1]);
        *(uint32_t*)&Nb[(size_t)(qloc + 8) * 256 + v * 8 + 2 * tig] = packh2(o[v][2], o[v][3]);
    }
    if (tig == 0) {
        Dbuf[((size_t)slot * 128 + qloc) * 8 + h] = l0;
        Dbuf[((size_t)slot * 128 + qloc + 8) * 8 + h] = l1;
    }
}

// =================== combine: sliding-window N/D -> G ===================
// Block = one token, 256 threads (one per head*dim column).
__global__ void __launch_bounds__(256)
combine_k(const __half* __restrict__ Nbuf, const float* __restrict__ Dbuf,
          __half* __restrict__ G)
{
    const int t = blockIdx.x;
    const int c = threadIdx.x;
    const int f = t >> 7, pos = t & 127;
    const int hh = c >> 5;

    const int ss[3]    = {2, 4, 6};
    const int strd[3]  = {3, 7, 11};
    const int sbase[3] = {SBASE0, SBASE1, SBASE2};

    #pragma unroll
    for (int si = 0; si < 3; si++) {
        const int s = ss[si];
        const int slotbase = sbase[si] + f * strd[si];
        const int nw = F - s + 1;
        const int wlo = max(0, f - s + 1);
        const int whi = min(f, nw - 1);
        const int count = whi - wlo + 1;

        // initial window (w = wlo): slots d in [wlo-f+s-1, wlo-f+2s-2]
        float num = 0.f, den = 0.f;
        const int d0 = wlo - f + s - 1;
        for (int dd = 0; dd < s; dd++) {
            int sl = slotbase + d0 + dd;
            num += __half2float(Nbuf[((size_t)sl * 128 + pos) * 256 + c]);
            den += Dbuf[((size_t)sl * 128 + pos) * 8 + hh];
        }
        float total = num / den;
        for (int w = wlo + 1; w <= whi; w++) {
            int slout = slotbase + (w - 1) - f + s - 1;
            int slin  = slotbase + w - f + 2 * s - 2;
            num += __half2float(Nbuf[((size_t)slin * 128 + pos) * 256 + c])
                 - __half2float(Nbuf[((size_t)slout * 128 + pos) * 256 + c]);
            den += Dbuf[((size_t)slin * 128 + pos) * 8 + hh]
                 - Dbuf[((size_t)slout * 128 + pos) * 8 + hh];
            total += num / den;
        }
        G[(size_t)t * KG + si * HH + c] = __float2half(total * (0.25f / (float)count));
    }
}

// =================== gproj GEMM [2304x768]@[768x256] + fused colsum/X epilogue ===================
__global__ void __launch_bounds__(256)
gemm_gproj_mma_k(const __half* __restrict__ G, const __half* __restrict__ Wgt,
                 const float* __restrict__ bsum, float* __restrict__ vsum,
                 __half* __restrict__ Xh, int writeX)
{
    __shared__ uint32_t sbuf[4 * GBUF];
    int bm = blockIdx.x * 128, bn = blockIdx.y * 128;

    float acc[2][8][4];
    mma_mainloop(G, bm, KG, Wgt, bn, KG, KG, sbuf, acc);

    const int tid  = threadIdx.x;
    const int warp = tid >> 5;
    const int lane = tid & 31;
    const int gid  = lane >> 2;
    const int tig  = lane & 3;
    const int wm = (warp & 3) * 32;
    const int wn = (warp >> 2) * 64;
    const int f = bm >> 7;
    float* vs = vsum + f * HH;

    #pragma unroll
    for (int nt = 0; nt < 8; nt++) {
        int n = bn + wn + nt * 8 + 2 * tig;
        float b0 = bsum[n], b1 = bsum[n + 1];
        float s0 = acc[0][nt][0] + acc[0][nt][2] + acc[1][nt][0] + acc[1][nt][2];
        float s1 = acc[0][nt][1] + acc[0][nt][3] + acc[1][nt][1] + acc[1][nt][3];
        #pragma unroll
        for (int off = 4; off < 32; off <<= 1) {
            s0 += __shfl_xor_sync(0xffffffffu, s0, off);
            s1 += __shfl_xor_sync(0xffffffffu, s1, off);
        }
        if (gid == 0) {
            atomicAdd(&vs[n], s0);
            atomicAdd(&vs[n + 1], s1);
        }
        if (writeX) {
            #pragma unroll
            for (int mt = 0; mt < 2; mt++) {
                int m = bm + wm + mt * 16 + gid;
                *(uint32_t*)&Xh[(size_t)m * 256 + n] =
                    packh2(acc[mt][nt][0] + b0, acc[mt][nt][1] + b1);
                *(uint32_t*)&Xh[(size_t)(m + 8) * 256 + n] =
                    packh2(acc[mt][nt][2] + b0, acc[mt][nt][3] + b1);
            }
        }
    }
}

// =================== classifier (combines per-iter colsums) ===================
__global__ void classify_k(const float* __restrict__ vsum, const float* __restrict__ warr,
                           const float* __restrict__ bsum,
                           const float* __restrict__ clsW, const float* __restrict__ clsb,
                           float* __restrict__ out)
{
    __shared__ float cs[HH];
    int tid = threadIdx.x;
    for (int h = tid; h < HH; h += 128) {
        float s = 0.f;
        float bb = 128.f * bsum[h];
        #pragma unroll
        for (int f = 0; f < F; f++) {
            float w0 = warr[f], w1 = warr[F + f];
            float v0 = vsum[f * HH + h] + bb;
            float v1 = vsum[F * HH + f * HH + h] + bb;
            s += w1 * v1 + (1.f - w1) * w0 * v0;
        }
        cs[h] = s;
    }
    __syncthreads();
    int j = blockIdx.x * 128 + tid;
    if (j < NCLS) {
        float acc = clsb[j];
        for (int h = 0; h < HH; h++) acc = fmaf(cs[h], clsW[h * NCLS + j], acc);
        out[j] = acc;
    }
}

// =================== host launch ===================
extern "C" void kernel_launch(void* const* d_in, const int* in_sizes, int n_in,
                              void* d_out, int out_size)
{
    (void)in_sizes; (void)n_in; (void)out_size;
    const float* embed  = (const float*)d_in[0];
    const float* halt_W = (const float*)d_in[3];
    const float* halt_b = (const float*)d_in[4];
    const float* cls_W  = (const float*)d_in[8];
    const float* cls_b  = (const float*)d_in[9];
    const float* Wq = (const float*)d_in[10];
    const float* bq = (const float*)d_in[11];
    const float* Wk = (const float*)d_in[12];
    const float* bk = (const float*)d_in[13];
    const float* Wv = (const float*)d_in[14];
    const float* bv = (const float*)d_in[15];
    const float* Wo = (const float*)d_in[16];
    const float* bo = (const float*)d_in[17];
    float* out = (float*)d_out;

    float *sig, *ptn, *Rt, *warr, *bsum, *vsum, *Dbuf;
    __half *Xh, *Qh, *Kh, *Nbuf, *G, *Wqkvh, *Wgt;
    uint32_t *Vt;
    cudaGetSymbolAddress((void**)&Xh,      d_Xh);
    cudaGetSymbolAddress((void**)&Qh,      d_Qh);
    cudaGetSymbolAddress((void**)&Kh,      d_Kh);
    cudaGetSymbolAddress((void**)&Vt,      d_Vt);
    cudaGetSymbolAddress((void**)&Nbuf,    d_Nbuf);
    cudaGetSymbolAddress((void**)&Dbuf,    d_Dbuf);
    cudaGetSymbolAddress((void**)&G,       d_G);
    cudaGetSymbolAddress((void**)&Wqkvh,   d_Wqkvh);
    cudaGetSymbolAddress((void**)&Wgt,     d_Wgt);
    cudaGetSymbolAddress((void**)&bsum,    d_bsum);
    cudaGetSymbolAddress((void**)&vsum,    d_vsum);
    cudaGetSymbolAddress((void**)&sig,     d_sig);
    cudaGetSymbolAddress((void**)&ptn,     d_ptn);
    cudaGetSymbolAddress((void**)&Rt,      d_Rt);
    cudaGetSymbolAddress((void**)&warr,    d_warr);

    // weight conversions (once per call)
    {
        dim3 b(32, 8);
        dim3 gq(8, 8, 9);
        convwt_qkv_k<<<gq, b>>>(Wq, Wk, Wv, Wqkvh);
        dim3 gg(8, 8, 3);
        convwt_gproj_k<<<gg, b>>>(Wo, Wgt);
        bsum_k<<<1, 256>>>(bo, bsum);
    }
    // iter-0 halting + fp16 X conversion (fused)
    halt_sig_k<<<TPAIRS / 8, 256>>>(embed, halt_W, halt_b, sig, Xh);

    for (int iter = 0; iter < 2; iter++) {
        act2_k<<<1, 576>>>(sig, ptn, Rt, warr, vsum, iter);

        // QKV (fp16 tensor GEMM) for all 3 scales; V written transposed (Vt)
        dim3 gq(NTOK / 128, 2, 9);
        gemm_qkv_mma_k<<<gq, 256>>>(Xh, Wqkvh, bq, bk, bv, Qh, Kh, Vt);

        // frame-pair attention (N/D decomposition): 378 slots x 8 heads
        dim3 ga(NSLOTS, 8);
        attn_nd_k<<<ga, 256>>>(Qh, Kh, Vt, Nbuf, Dbuf);

        // sliding-window combine -> G
        combine_k<<<NTOK, 256>>>(Nbuf, Dbuf, G);

        // fused projection GEMM + per-frame colsum (+Xh for next iter)
        dim3 gg(NTOK / 128, 2);
        gemm_gproj_mma_k<<<gg, 256>>>(G, Wgt, bsum, vsum + iter * F * HH, Xh,
                                      iter == 0 ? 1 : 0);

        // halting sigmoid for next iteration (reads fp16 Xh)
        if (iter == 0)
            halt_sig_h_k<<<TPAIRS / 8, 256>>>(Xh, halt_W, halt_b, sig);
    }
    classify_k<<<(NCLS + 127) / 128, 128>>>(vsum, warr, bsum, cls_W, cls_b, out);
}